// round 4
// baseline (speedup 1.0000x reference)
#include <cuda_runtime.h>
#include <cuda_bf16.h>

// LearnablePeakExtractor: smooth = x * sig(10*(x-thresh)) * sig(10*(x-pooled5))
//                         mask   = smooth >= thresh
// Fused: sig(a)*sig(b) = 1/((1+e^-a)(1+e^-b)) -> 2 EX2 + 1 RCP per element.
// R4: exact R3 kernel; stores switched to .cs (evict-streaming) so output
//     write lines don't evict the (almost exactly L2-sized) input between
//     graph replays.

#define ROWS 256
#define LEN  131072
#define VPR  (LEN / 4)   // float4 vectors per row = 32768

__device__ __forceinline__ float fused2(float x, float thresh, float pooled) {
    float e1 = __expf(10.0f * (thresh - x));
    float e2 = __expf(10.0f * (pooled - x));
    return __fdividef(x, (1.0f + e1) * (1.0f + e2));
}

__global__ __launch_bounds__(256)
void peak_kernel(const float* __restrict__ in,
                 const float* __restrict__ logit_thresh,
                 float* __restrict__ out_smooth,
                 float* __restrict__ out_mask,
                 int write_mask)
{
    const int row  = blockIdx.y;
    const int vc   = blockIdx.x * blockDim.x + threadIdx.x;  // vec4 index in row
    const unsigned lane = threadIdx.x & 31;

    const float* rowp = in + (size_t)row * LEN;
    const float4* rp  = reinterpret_cast<const float4*>(rowp);

    float4 c = rp[vc];

    // neighbor halo via warp shuffle; only warp-edge lanes touch memory
    float lx = __shfl_up_sync(0xFFFFFFFFu,   c.z, 1);
    float ly = __shfl_up_sync(0xFFFFFFFFu,   c.w, 1);
    float rx = __shfl_down_sync(0xFFFFFFFFu, c.x, 1);
    float ry = __shfl_down_sync(0xFFFFFFFFu, c.y, 1);

    if (lane == 0) {
        if (vc > 0) {
            float2 p = *reinterpret_cast<const float2*>(rowp + 4 * vc - 2);
            lx = p.x; ly = p.y;
        } else {
            lx = c.x; ly = c.x;      // edge replicate
        }
    }
    if (lane == 31) {
        if (vc < VPR - 1) {
            float2 n = *reinterpret_cast<const float2*>(rowp + 4 * vc + 4);
            rx = n.x; ry = n.y;
        } else {
            rx = c.w; ry = c.w;      // edge replicate
        }
    }

    // 5-wide sliding max
    float m01   = fmaxf(c.x, c.y);
    float m12   = fmaxf(c.y, c.z);
    float m23   = fmaxf(c.z, c.w);
    float m012  = fmaxf(m01, c.z);
    float m123  = fmaxf(m12, c.w);
    float m0123 = fmaxf(m01, m23);

    float p0 = fmaxf(fmaxf(lx, ly), m012);
    float p1 = fmaxf(ly, m0123);
    float p2 = fmaxf(m0123, rx);
    float p3 = fmaxf(m123, fmaxf(rx, ry));

    float tl = logit_thresh[0];
    float thresh = __fdividef(1.0f, 1.0f + __expf(-tl));

    float s0 = fused2(c.x, thresh, p0);
    float s1 = fused2(c.y, thresh, p1);
    float s2 = fused2(c.z, thresh, p2);
    float s3 = fused2(c.w, thresh, p3);

    const size_t voff = (size_t)row * VPR + vc;
    __stcs(reinterpret_cast<float4*>(out_smooth) + voff,
           make_float4(s0, s1, s2, s3));

    if (write_mask) {
        __stcs(reinterpret_cast<float4*>(out_mask) + voff,
               make_float4(s0 >= thresh ? 1.0f : 0.0f,
                           s1 >= thresh ? 1.0f : 0.0f,
                           s2 >= thresh ? 1.0f : 0.0f,
                           s3 >= thresh ? 1.0f : 0.0f));
    }
}

extern "C" void kernel_launch(void* const* d_in, const int* in_sizes, int n_in,
                              void* d_out, int out_size)
{
    const float* peak_map     = (const float*)d_in[0];
    const float* logit_thresh = (const float*)d_in[1];
    float* out = (float*)d_out;

    const long long N = (long long)ROWS * LEN;   // 33,554,432
    int write_mask = (out_size >= 2 * N) ? 1 : 0;

    dim3 grid(VPR / 256, ROWS);   // (128, 256)
    peak_kernel<<<grid, 256>>>(peak_map, logit_thresh,
                               out, out + N, write_mask);
}

// round 5
// speedup vs baseline: 1.0428x; 1.0428x over previous
#include <cuda_runtime.h>
#include <cuda_bf16.h>

// LearnablePeakExtractor: smooth = x * sig(10*(x-thresh)) * sig(10*(x-pooled5))
//                         mask   = smooth >= thresh
// Fused: sig(a)*sig(b) = 1/((1+e^-a)(1+e^-b)) -> 2 EX2 + 1 RCP per element.
// R5: Blackwell 256-bit ld/st (LDG.E.256 / STG.E.256), 8 floats/thread,
//     warp-shuffle halo, normal cache policy.

#define ROWS 256
#define LEN  131072
#define CH   (LEN / 8)   // 8-elem chunks per row = 16384

__device__ __forceinline__ float fused2(float x, float thresh, float pooled) {
    float e1 = __expf(10.0f * (thresh - x));
    float e2 = __expf(10.0f * (pooled - x));
    return __fdividef(x, (1.0f + e1) * (1.0f + e2));
}

__device__ __forceinline__ void ldg256(const float* p, float* r) {
    asm volatile("ld.global.v8.f32 {%0,%1,%2,%3,%4,%5,%6,%7}, [%8];"
                 : "=f"(r[0]), "=f"(r[1]), "=f"(r[2]), "=f"(r[3]),
                   "=f"(r[4]), "=f"(r[5]), "=f"(r[6]), "=f"(r[7])
                 : "l"(p));
}

__device__ __forceinline__ void stg256(float* p, const float* r) {
    asm volatile("st.global.v8.f32 [%0], {%1,%2,%3,%4,%5,%6,%7,%8};"
                 :: "l"(p),
                    "f"(r[0]), "f"(r[1]), "f"(r[2]), "f"(r[3]),
                    "f"(r[4]), "f"(r[5]), "f"(r[6]), "f"(r[7])
                 : "memory");
}

__global__ __launch_bounds__(256)
void peak_kernel(const float* __restrict__ in,
                 const float* __restrict__ logit_thresh,
                 float* __restrict__ out_smooth,
                 float* __restrict__ out_mask,
                 int write_mask)
{
    const int row = blockIdx.y;
    const int t   = blockIdx.x * blockDim.x + threadIdx.x;   // chunk index in row
    const unsigned lane = threadIdx.x & 31;

    const float* rowp = in + (size_t)row * LEN;
    const float* base = rowp + 8 * (size_t)t;

    float e[8];
    ldg256(base, e);

    // halo via warp shuffle; only warp-edge lanes touch memory
    float lx = __shfl_up_sync(0xFFFFFFFFu,   e[6], 1);
    float ly = __shfl_up_sync(0xFFFFFFFFu,   e[7], 1);
    float rx = __shfl_down_sync(0xFFFFFFFFu, e[0], 1);
    float ry = __shfl_down_sync(0xFFFFFFFFu, e[1], 1);

    if (lane == 0) {
        if (t > 0) {
            float2 p = *reinterpret_cast<const float2*>(base - 2);
            lx = p.x; ly = p.y;
        } else {
            lx = e[0]; ly = e[0];    // edge replicate
        }
    }
    if (lane == 31) {
        if (t < CH - 1) {
            float2 n = *reinterpret_cast<const float2*>(base + 8);
            rx = n.x; ry = n.y;
        } else {
            rx = e[7]; ry = e[7];    // edge replicate
        }
    }

    // 5-wide sliding max over e[0..7] with halo (lx,ly | rx,ry)
    float M01 = fmaxf(e[0], e[1]);
    float M23 = fmaxf(e[2], e[3]);
    float M45 = fmaxf(e[4], e[5]);
    float M67 = fmaxf(e[6], e[7]);
    float Mll = fmaxf(lx, ly);
    float Mrr = fmaxf(rx, ry);

    float p[8];
    p[0] = fmaxf(Mll,  fmaxf(M01, e[2]));
    p[1] = fmaxf(ly,   fmaxf(M01, M23));
    p[2] = fmaxf(M01,  fmaxf(M23, e[4]));
    p[3] = fmaxf(e[1], fmaxf(M23, M45));
    p[4] = fmaxf(e[2], fmaxf(M23, fmaxf(M45, e[6])));
    p[5] = fmaxf(e[3], fmaxf(M45, M67));
    p[6] = fmaxf(M45,  fmaxf(M67, rx));
    p[7] = fmaxf(e[5], fmaxf(M67, Mrr));

    float tl = logit_thresh[0];
    float thresh = __fdividef(1.0f, 1.0f + __expf(-tl));

    float s[8];
#pragma unroll
    for (int i = 0; i < 8; i++)
        s[i] = fused2(e[i], thresh, p[i]);

    const size_t off = (size_t)row * LEN + 8 * (size_t)t;
    stg256(out_smooth + off, s);

    if (write_mask) {
        float m[8];
#pragma unroll
        for (int i = 0; i < 8; i++)
            m[i] = (s[i] >= thresh) ? 1.0f : 0.0f;
        stg256(out_mask + off, m);
    }
}

extern "C" void kernel_launch(void* const* d_in, const int* in_sizes, int n_in,
                              void* d_out, int out_size)
{
    const float* peak_map     = (const float*)d_in[0];
    const float* logit_thresh = (const float*)d_in[1];
    float* out = (float*)d_out;

    const long long N = (long long)ROWS * LEN;   // 33,554,432
    int write_mask = (out_size >= 2 * N) ? 1 : 0;

    dim3 grid(CH / 256, ROWS);   // (64, 256)
    peak_kernel<<<grid, 256>>>(peak_map, logit_thresh,
                               out, out + N, write_mask);
}